// round 1
// baseline (speedup 1.0000x reference)
#include <cuda_runtime.h>

// GCN on complete graph + self-loops collapses to per-batch mean pooling:
// every node of a batch element gets mean_j(h[j]) after each GCN layer, so
// the whole net is a per-batch-element 4-layer MLP on the mean feature.

#define ROWS 8     // batch rows per block
#define NT   128   // threads per block

__global__ __launch_bounds__(NT) void gcnn_actor_kernel(
    const float* __restrict__ obs,
    const float* __restrict__ W1,  const float* __restrict__ b1,
    const float* __restrict__ W2,  const float* __restrict__ b2,
    const float* __restrict__ Wm1, const float* __restrict__ bm1,
    const float* __restrict__ Wm2, const float* __restrict__ bm2,
    float* __restrict__ out, int std_off)
{
    __shared__ float sObs[ROWS * 512];   // staged obs rows
    __shared__ float sA[ROWS * 128];     // h1, then m
    __shared__ float sB[ROWS * 128];     // h2
    __shared__ float sF[ROWS * 16];      // fbar, then o

    const int tid  = threadIdx.x;
    const int base = blockIdx.x * ROWS;

    // ---- stage obs rows (coalesced float4) ----
    {
        const float4* g4 = reinterpret_cast<const float4*>(obs + (size_t)base * 512);
        float4* s4 = reinterpret_cast<float4*>(sObs);
        #pragma unroll
        for (int i = tid; i < ROWS * 512 / 4; i += NT) s4[i] = g4[i];
    }
    __syncthreads();

    // ---- fbar[r][d] = mean over 32 nodes of obs[., n*16 + 2 + d] ----
    if (tid < ROWS * 14) {
        const int r = tid / 14, d = tid % 14;
        float s = 0.f;
        #pragma unroll
        for (int n = 0; n < 32; n++) s += sObs[r * 512 + n * 16 + 2 + d];
        sF[r * 16 + d] = s * (1.0f / 32.0f);
    }
    __syncthreads();

    // ---- h1 = relu(fbar @ W1 + b1) : sF -> sA ----
    {
        float w[14];
        #pragma unroll
        for (int d = 0; d < 14; d++) w[d] = W1[d * 128 + tid];
        const float bb = b1[tid];
        #pragma unroll
        for (int r = 0; r < ROWS; r++) {
            float acc = bb;
            #pragma unroll
            for (int d = 0; d < 14; d++) acc = fmaf(sF[r * 16 + d], w[d], acc);
            sA[r * 128 + tid] = fmaxf(acc, 0.f);
        }
    }
    __syncthreads();

    // ---- h2 = relu(h1 @ W2 + b2) : sA -> sB ----
    {
        float acc[ROWS];
        const float bb = b2[tid];
        #pragma unroll
        for (int r = 0; r < ROWS; r++) acc[r] = bb;
        #pragma unroll 8
        for (int k = 0; k < 128; k++) {
            const float w = W2[k * 128 + tid];   // coalesced, L2-resident
            #pragma unroll
            for (int r = 0; r < ROWS; r++)
                acc[r] = fmaf(sA[r * 128 + k], w, acc[r]);
        }
        #pragma unroll
        for (int r = 0; r < ROWS; r++)
            sB[r * 128 + tid] = fmaxf(acc[r], 0.f);
    }
    __syncthreads();

    // ---- m = relu(h2 @ Wm1 + bm1) : sB -> sA ----
    {
        float acc[ROWS];
        const float bb = bm1[tid];
        #pragma unroll
        for (int r = 0; r < ROWS; r++) acc[r] = bb;
        #pragma unroll 8
        for (int k = 0; k < 128; k++) {
            const float w = Wm1[k * 128 + tid];
            #pragma unroll
            for (int r = 0; r < ROWS; r++)
                acc[r] = fmaf(sB[r * 128 + k], w, acc[r]);
        }
        #pragma unroll
        for (int r = 0; r < ROWS; r++)
            sA[r * 128 + tid] = fmaxf(acc[r], 0.f);
    }
    __syncthreads();

    // ---- o = m @ Wm2 + bm2 : 32 threads, 4 outputs per row ----
    if (tid < ROWS * 4) {
        const int r = tid >> 2, c = tid & 3;
        float acc = bm2[c];
        #pragma unroll 8
        for (int k = 0; k < 128; k++)
            acc = fmaf(sA[r * 128 + k], Wm2[k * 4 + c], acc);
        sF[r * 16 + c] = acc;   // fbar dead, reuse
    }
    __syncthreads();

    // ---- write: mu replicated x32, std = exp(-5 + 3.5*(tanh(o)+1)) x32 ----
    #pragma unroll
    for (int r = 0; r < ROWS; r++) {
        const size_t b = (size_t)(base + r);
        if (tid < 64) {
            out[b * 64 + tid] = sF[r * 16 + (tid & 1)];
        } else {
            const int jj = tid - 64;
            const float lc = sF[r * 16 + 2 + (jj & 1)];
            const float t  = tanhf(lc);
            const float ls = -5.0f + 3.5f * (t + 1.0f);
            out[(size_t)std_off + b * 64 + jj] = expf(ls);
        }
    }
}

extern "C" void kernel_launch(void* const* d_in, const int* in_sizes, int n_in,
                              void* d_out, int out_size) {
    const float* obs = (const float*)d_in[0];
    const float* W1  = (const float*)d_in[1];
    const float* b1  = (const float*)d_in[2];
    const float* W2  = (const float*)d_in[3];
    const float* b2  = (const float*)d_in[4];
    const float* Wm1 = (const float*)d_in[5];
    const float* bm1 = (const float*)d_in[6];
    const float* Wm2 = (const float*)d_in[7];
    const float* bm2 = (const float*)d_in[8];
    float* out = (float*)d_out;

    const int bs = in_sizes[0] / 512;        // 1024
    const int std_off = bs * 64;             // offset of std plane in out
    const int grid = bs / ROWS;              // 128 blocks

    gcnn_actor_kernel<<<grid, NT>>>(obs, W1, b1, W2, b2, Wm1, bm1, Wm2, bm2,
                                    out, std_off);
}

// round 2
// speedup vs baseline: 1.3175x; 1.3175x over previous
#include <cuda_runtime.h>
#include <cstdint>

// GCN on complete graph + self-loops == per-batch mean pooling, so the net
// collapses to a per-batch-element 4-layer MLP on the mean node feature.
// This version bulk-stages ALL operands (obs slice + every weight/bias) into
// shared memory with cp.async.bulk (TMA) + mbarrier, then runs the MLP out of
// SMEM so the hot loops are FMA-pipe bound instead of L2-latency bound.

#define ROWS 8
#define NT   128

// ---- smem layout (floats) ----
#define OFF_OBS   0
#define N_OBS     (ROWS * 512)          // 4096
#define OFF_W1    (OFF_OBS + N_OBS)     // 4096
#define N_W1      (14 * 128)            // 1792
#define OFF_B1    (OFF_W1 + N_W1)
#define OFF_W2    (OFF_B1 + 128)
#define N_W2      (128 * 128)
#define OFF_B2    (OFF_W2 + N_W2)
#define OFF_WM1   (OFF_B2 + 128)
#define OFF_BM1   (OFF_WM1 + N_W2)
#define OFF_WM2   (OFF_BM1 + 128)
#define N_WM2     (128 * 4)
#define OFF_BM2   (OFF_WM2 + N_WM2)     // 4 floats (16B)
#define OFF_A     (OFF_BM2 + 4)
#define OFF_B     (OFF_A + ROWS * 128)
#define OFF_F     (OFF_B + ROWS * 128)
#define OFF_MBAR  (OFF_F + ROWS * 16)   // 2 x u64
#define SMEM_FLOATS (OFF_MBAR + 4)
#define SMEM_BYTES  (SMEM_FLOATS * 4)

#define BYTES_A ((N_OBS + N_W1 + 128) * 4)
#define BYTES_B ((N_W2 + 128 + N_W2 + 128 + N_WM2 + 4) * 4)

__device__ __forceinline__ uint32_t s2u(const void* p) {
    return (uint32_t)__cvta_generic_to_shared(p);
}
__device__ __forceinline__ void mbar_init(uint32_t a, uint32_t cnt) {
    asm volatile("mbarrier.init.shared.b64 [%0], %1;" :: "r"(a), "r"(cnt) : "memory");
}
__device__ __forceinline__ void mbar_expect(uint32_t a, uint32_t bytes) {
    asm volatile("mbarrier.arrive.expect_tx.shared.b64 _, [%0], %1;"
                 :: "r"(a), "r"(bytes) : "memory");
}
__device__ __forceinline__ void bulk_g2s(uint32_t dst, const void* src,
                                         uint32_t bytes, uint32_t mbar) {
    asm volatile("cp.async.bulk.shared::cluster.global.mbarrier::complete_tx::bytes "
                 "[%0], [%1], %2, [%3];"
                 :: "r"(dst), "l"(src), "r"(bytes), "r"(mbar) : "memory");
}
__device__ __forceinline__ void mbar_wait(uint32_t a, uint32_t parity) {
    asm volatile(
        "{\n\t.reg .pred P;\n"
        "WAIT_%=:\n\t"
        "mbarrier.try_wait.parity.shared.b64 P, [%0], %1, 0x989680;\n\t"
        "@P bra.uni DONE_%=;\n\t"
        "bra.uni WAIT_%=;\n"
        "DONE_%=:\n\t}"
        :: "r"(a), "r"(parity) : "memory");
}

// out[r*128+tid] = relu( sum_k in[r*128+k] * W[k*128+tid] + b[tid] ), W,b,in,out in smem
__device__ __forceinline__ void dense128(const float* __restrict__ sIn,
                                         const float* __restrict__ sW,
                                         const float* __restrict__ sb,
                                         float* __restrict__ sOut, int tid) {
    float acc[ROWS];
    const float bb = sb[tid];
    #pragma unroll
    for (int r = 0; r < ROWS; r++) acc[r] = bb;
    const float4* sIn4 = reinterpret_cast<const float4*>(sIn);
    #pragma unroll 4
    for (int kq = 0; kq < 32; kq++) {
        const float w0 = sW[(4 * kq + 0) * 128 + tid];
        const float w1 = sW[(4 * kq + 1) * 128 + tid];
        const float w2 = sW[(4 * kq + 2) * 128 + tid];
        const float w3 = sW[(4 * kq + 3) * 128 + tid];
        #pragma unroll
        for (int r = 0; r < ROWS; r++) {
            const float4 a = sIn4[r * 32 + kq];
            acc[r] = fmaf(a.x, w0, acc[r]);
            acc[r] = fmaf(a.y, w1, acc[r]);
            acc[r] = fmaf(a.z, w2, acc[r]);
            acc[r] = fmaf(a.w, w3, acc[r]);
        }
    }
    #pragma unroll
    for (int r = 0; r < ROWS; r++) sOut[r * 128 + tid] = fmaxf(acc[r], 0.f);
}

__global__ __launch_bounds__(NT) void gcnn_actor_kernel(
    const float* __restrict__ obs,
    const float* __restrict__ W1,  const float* __restrict__ b1,
    const float* __restrict__ W2,  const float* __restrict__ b2,
    const float* __restrict__ Wm1, const float* __restrict__ bm1,
    const float* __restrict__ Wm2, const float* __restrict__ bm2,
    float* __restrict__ out, int std_off)
{
    extern __shared__ float sm[];
    float* sObs = sm + OFF_OBS;
    float* sA   = sm + OFF_A;
    float* sB   = sm + OFF_B;
    float* sF   = sm + OFF_F;

    const int tid  = threadIdx.x;
    const int base = blockIdx.x * ROWS;

    const uint32_t mbarA = s2u(sm + OFF_MBAR);
    const uint32_t mbarB = mbarA + 8;

    if (tid == 0) { mbar_init(mbarA, 1); mbar_init(mbarB, 1); }
    __syncthreads();

    if (tid == 0) {
        mbar_expect(mbarA, BYTES_A);
        bulk_g2s(s2u(sm + OFF_OBS), obs + (size_t)base * 512, N_OBS * 4, mbarA);
        bulk_g2s(s2u(sm + OFF_W1),  W1,  N_W1 * 4,  mbarA);
        bulk_g2s(s2u(sm + OFF_B1),  b1,  128 * 4,   mbarA);
        mbar_expect(mbarB, BYTES_B);
        bulk_g2s(s2u(sm + OFF_W2),  W2,  N_W2 * 4,  mbarB);
        bulk_g2s(s2u(sm + OFF_B2),  b2,  128 * 4,   mbarB);
        bulk_g2s(s2u(sm + OFF_WM1), Wm1, N_W2 * 4,  mbarB);
        bulk_g2s(s2u(sm + OFF_BM1), bm1, 128 * 4,   mbarB);
        bulk_g2s(s2u(sm + OFF_WM2), Wm2, N_WM2 * 4, mbarB);
        bulk_g2s(s2u(sm + OFF_BM2), bm2, 4 * 4,     mbarB);
    }

    // ---- wait for obs + layer-1 params ----
    mbar_wait(mbarA, 0);

    // fbar[r][d] = mean over 32 nodes of obs[., n*16 + 2 + d]
    if (tid < ROWS * 14) {
        const int r = tid / 14, d = tid % 14;
        float s = 0.f;
        #pragma unroll
        for (int n = 0; n < 32; n++) s += sObs[r * 512 + n * 16 + 2 + d];
        sF[r * 16 + d] = s * (1.0f / 32.0f);
    }
    __syncthreads();

    // h1 = relu(fbar @ W1 + b1) -> sA
    {
        float w[14];
        #pragma unroll
        for (int d = 0; d < 14; d++) w[d] = sm[OFF_W1 + d * 128 + tid];
        const float bb = sm[OFF_B1 + tid];
        #pragma unroll
        for (int r = 0; r < ROWS; r++) {
            float acc = bb;
            #pragma unroll
            for (int d = 0; d < 14; d++) acc = fmaf(sF[r * 16 + d], w[d], acc);
            sA[r * 128 + tid] = fmaxf(acc, 0.f);
        }
    }

    // ---- wait for remaining weights ----
    mbar_wait(mbarB, 0);
    __syncthreads();

    // h2 = relu(h1 @ W2 + b2) : sA -> sB
    dense128(sA, sm + OFF_W2, sm + OFF_B2, sB, tid);
    __syncthreads();

    // m = relu(h2 @ Wm1 + bm1) : sB -> sA
    dense128(sB, sm + OFF_WM1, sm + OFF_BM1, sA, tid);
    __syncthreads();

    // o = m @ Wm2 + bm2 : 128 threads = 8 rows x 4 cols x 4 k-slices
    {
        const int r = tid >> 4, c = (tid >> 2) & 3, s = tid & 3;
        float p = 0.f;
        #pragma unroll 8
        for (int i = 0; i < 32; i++) {
            const int k = s * 32 + i;
            p = fmaf(sA[r * 128 + k], sm[OFF_WM2 + k * 4 + c], p);
        }
        sB[tid] = p;  // sB dead, reuse as scratch
    }
    __syncthreads();
    if (tid < ROWS * 4) {
        const int r = tid >> 2, c = tid & 3;
        const int pbase = r * 16 + c * 4;
        const float o = sm[OFF_BM2 + c] + sB[pbase] + sB[pbase + 1]
                      + sB[pbase + 2] + sB[pbase + 3];
        sF[r * 16 + c] = o;
    }
    __syncthreads();

    // write: mu replicated x32, std = exp(-5 + 3.5*(tanh(o)+1)) replicated x32
    #pragma unroll
    for (int r = 0; r < ROWS; r++) {
        const size_t b = (size_t)(base + r);
        if (tid < 64) {
            out[b * 64 + tid] = sF[r * 16 + (tid & 1)];
        } else {
            const int jj = tid - 64;
            const float lc = sF[r * 16 + 2 + (jj & 1)];
            const float t  = tanhf(lc);
            out[(size_t)std_off + b * 64 + jj] = __expf(-5.0f + 3.5f * (t + 1.0f));
        }
    }
}

extern "C" void kernel_launch(void* const* d_in, const int* in_sizes, int n_in,
                              void* d_out, int out_size) {
    const float* obs = (const float*)d_in[0];
    const float* W1  = (const float*)d_in[1];
    const float* b1  = (const float*)d_in[2];
    const float* W2  = (const float*)d_in[3];
    const float* b2  = (const float*)d_in[4];
    const float* Wm1 = (const float*)d_in[5];
    const float* bm1 = (const float*)d_in[6];
    const float* Wm2 = (const float*)d_in[7];
    const float* bm2 = (const float*)d_in[8];
    float* out = (float*)d_out;

    const int bs = in_sizes[0] / 512;
    const int std_off = bs * 64;
    const int grid = bs / ROWS;

    cudaFuncSetAttribute(gcnn_actor_kernel,
                         cudaFuncAttributeMaxDynamicSharedMemorySize, SMEM_BYTES);
    gcnn_actor_kernel<<<grid, NT, SMEM_BYTES>>>(obs, W1, b1, W2, b2, Wm1, bm1,
                                                Wm2, bm2, out, std_off);
}

// round 3
// speedup vs baseline: 1.5731x; 1.1940x over previous
#include <cuda_runtime.h>
#include <cstdint>

// GCN on complete graph + self-loops == per-batch mean pooling, so the net
// collapses to a per-batch-element 4-layer MLP on the mean node feature.
// TMA-staged weights, 256 threads/CTA (2 warps/SMSP), row-pair-packed
// activations with fma.rn.f32x2 in the two 128x128 dense layers.

#define ROWS 8
#define NT   256

// ---- smem layout (floats) ----
#define OFF_OBS   0
#define N_OBS     (ROWS * 512)          // 4096
#define OFF_W1    (OFF_OBS + N_OBS)
#define N_W1      (14 * 128)            // 1792
#define OFF_B1    (OFF_W1 + N_W1)       // 5888
#define OFF_W2    (OFF_B1 + 128)        // 6016
#define N_W2      (128 * 128)
#define OFF_B2    (OFF_W2 + N_W2)       // 22400
#define OFF_WM1   (OFF_B2 + 128)        // 22528
#define OFF_BM1   (OFF_WM1 + N_W2)      // 38912
#define OFF_WM2   (OFF_BM1 + 128)       // 39040
#define N_WM2     (128 * 4)
#define OFF_BM2   (OFF_WM2 + N_WM2)     // 39552
#define OFF_A     (OFF_BM2 + 4)         // 39556 (16B aligned: *4 % 16 == 0)
#define OFF_B     (OFF_A + ROWS * 128)  // 40580
#define OFF_F     (OFF_B + ROWS * 128)  // 41604
#define OFF_MBAR  (OFF_F + ROWS * 16)   // 41732 (8B aligned)
#define SMEM_FLOATS (OFF_MBAR + 8)
#define SMEM_BYTES  (SMEM_FLOATS * 4)

#define BYTES_A ((N_OBS + N_W1 + 128) * 4)        // obs + W1 + b1
#define BYTES_B ((N_W2 + 128) * 4)                // W2 + b2
#define BYTES_C ((N_W2 + 128 + N_WM2 + 4) * 4)    // Wm1 + bm1 + Wm2 + bm2

__device__ __forceinline__ uint32_t s2u(const void* p) {
    return (uint32_t)__cvta_generic_to_shared(p);
}
__device__ __forceinline__ void mbar_init(uint32_t a, uint32_t cnt) {
    asm volatile("mbarrier.init.shared.b64 [%0], %1;" :: "r"(a), "r"(cnt) : "memory");
}
__device__ __forceinline__ void mbar_expect(uint32_t a, uint32_t bytes) {
    asm volatile("mbarrier.arrive.expect_tx.shared.b64 _, [%0], %1;"
                 :: "r"(a), "r"(bytes) : "memory");
}
__device__ __forceinline__ void bulk_g2s(uint32_t dst, const void* src,
                                         uint32_t bytes, uint32_t mbar) {
    asm volatile("cp.async.bulk.shared::cluster.global.mbarrier::complete_tx::bytes "
                 "[%0], [%1], %2, [%3];"
                 :: "r"(dst), "l"(src), "r"(bytes), "r"(mbar) : "memory");
}
__device__ __forceinline__ void mbar_wait(uint32_t a, uint32_t parity) {
    asm volatile(
        "{\n\t.reg .pred P;\n"
        "WAIT_%=:\n\t"
        "mbarrier.try_wait.parity.shared.b64 P, [%0], %1, 0x989680;\n\t"
        "@P bra.uni DONE_%=;\n\t"
        "bra.uni WAIT_%=;\n"
        "DONE_%=:\n\t}"
        :: "r"(a), "r"(parity) : "memory");
}

// ---- packed f32x2 helpers ----
__device__ __forceinline__ unsigned long long pk(float x, float y) {
    unsigned long long r;
    asm("mov.b64 %0, {%1, %2};" : "=l"(r) : "f"(x), "f"(y));
    return r;
}
__device__ __forceinline__ void fma2(unsigned long long& c,
                                     unsigned long long a, unsigned long long b) {
    asm("fma.rn.f32x2 %0, %1, %2, %3;" : "=l"(c) : "l"(a), "l"(b), "l"(c));
}
__device__ __forceinline__ float2 upk(unsigned long long v) {
    float2 r;
    asm("mov.b64 {%0, %1}, %2;" : "=f"(r.x), "=f"(r.y) : "l"(v));
    return r;
}

// Dense 128->128, activations packed as row-pairs:
// sIn float layout: pair p (rows 2p,2p+1): sIn[p*256 + 2k + e] = act[row 2p+e][k]
// Thread (col = tid&127, h = tid>>7) produces rows 4h..4h+3 (pairs 2h, 2h+1) at col.
__device__ __forceinline__ void dense128p(const float* __restrict__ sIn,
                                          const float* __restrict__ sW,
                                          const float* __restrict__ sb,
                                          float* __restrict__ sOut,
                                          int col, int h) {
    const float bb = sb[col];
    unsigned long long accA = pk(bb, bb);
    unsigned long long accB = accA;
    const ulonglong2* inA = reinterpret_cast<const ulonglong2*>(sIn + (2 * h) * 256);
    const ulonglong2* inB = reinterpret_cast<const ulonglong2*>(sIn + (2 * h + 1) * 256);
    #pragma unroll 8
    for (int kq = 0; kq < 32; kq++) {
        const float w0 = sW[(4 * kq + 0) * 128 + col];
        const float w1 = sW[(4 * kq + 1) * 128 + col];
        const float w2 = sW[(4 * kq + 2) * 128 + col];
        const float w3 = sW[(4 * kq + 3) * 128 + col];
        const unsigned long long wp0 = pk(w0, w0);
        const unsigned long long wp1 = pk(w1, w1);
        const unsigned long long wp2 = pk(w2, w2);
        const unsigned long long wp3 = pk(w3, w3);
        const ulonglong2 a0 = inA[2 * kq], a1 = inA[2 * kq + 1];
        const ulonglong2 b0 = inB[2 * kq], b1 = inB[2 * kq + 1];
        fma2(accA, a0.x, wp0); fma2(accA, a0.y, wp1);
        fma2(accA, a1.x, wp2); fma2(accA, a1.y, wp3);
        fma2(accB, b0.x, wp0); fma2(accB, b0.y, wp1);
        fma2(accB, b1.x, wp2); fma2(accB, b1.y, wp3);
    }
    float2 vA = upk(accA), vB = upk(accB);
    vA.x = fmaxf(vA.x, 0.f); vA.y = fmaxf(vA.y, 0.f);
    vB.x = fmaxf(vB.x, 0.f); vB.y = fmaxf(vB.y, 0.f);
    reinterpret_cast<float2*>(sOut)[(2 * h) * 128 + col]     = vA;
    reinterpret_cast<float2*>(sOut)[(2 * h + 1) * 128 + col] = vB;
}

__global__ __launch_bounds__(NT) void gcnn_actor_kernel(
    const float* __restrict__ obs,
    const float* __restrict__ W1,  const float* __restrict__ b1,
    const float* __restrict__ W2,  const float* __restrict__ b2,
    const float* __restrict__ Wm1, const float* __restrict__ bm1,
    const float* __restrict__ Wm2, const float* __restrict__ bm2,
    float* __restrict__ out, int std_off)
{
    extern __shared__ float sm[];
    float* sObs = sm + OFF_OBS;
    float* sA   = sm + OFF_A;
    float* sB   = sm + OFF_B;
    float* sF   = sm + OFF_F;

    const int tid  = threadIdx.x;
    const int col  = tid & 127;
    const int h    = tid >> 7;
    const int base = blockIdx.x * ROWS;

    const uint32_t mbarA = s2u(sm + OFF_MBAR);
    const uint32_t mbarB = mbarA + 8;
    const uint32_t mbarC = mbarA + 16;

    if (tid == 0) { mbar_init(mbarA, 1); mbar_init(mbarB, 1); mbar_init(mbarC, 1); }
    __syncthreads();

    if (tid == 0) {
        mbar_expect(mbarA, BYTES_A);
        bulk_g2s(s2u(sm + OFF_OBS), obs + (size_t)base * 512, N_OBS * 4, mbarA);
        bulk_g2s(s2u(sm + OFF_W1),  W1,  N_W1 * 4,  mbarA);
        bulk_g2s(s2u(sm + OFF_B1),  b1,  128 * 4,   mbarA);
        mbar_expect(mbarB, BYTES_B);
        bulk_g2s(s2u(sm + OFF_W2),  W2,  N_W2 * 4,  mbarB);
        bulk_g2s(s2u(sm + OFF_B2),  b2,  128 * 4,   mbarB);
        mbar_expect(mbarC, BYTES_C);
        bulk_g2s(s2u(sm + OFF_WM1), Wm1, N_W2 * 4,  mbarC);
        bulk_g2s(s2u(sm + OFF_BM1), bm1, 128 * 4,   mbarC);
        bulk_g2s(s2u(sm + OFF_WM2), Wm2, N_WM2 * 4, mbarC);
        bulk_g2s(s2u(sm + OFF_BM2), bm2, 4 * 4,     mbarC);
    }

    // ---- obs + layer-1 params ----
    mbar_wait(mbarA, 0);

    // fbar[r][d] = mean over 32 nodes of obs[., n*16 + 2 + d]
    if (tid < ROWS * 14) {
        const int r = tid / 14, d = tid % 14;
        float s = 0.f;
        #pragma unroll
        for (int n = 0; n < 32; n++) s += sObs[r * 512 + n * 16 + 2 + d];
        sF[r * 16 + d] = s * (1.0f / 32.0f);
    }
    __syncthreads();

    // h1 = relu(fbar @ W1 + b1) -> sA (packed row-pair layout)
    {
        float w[14];
        #pragma unroll
        for (int d = 0; d < 14; d++) w[d] = sm[OFF_W1 + d * 128 + col];
        const float bb = sm[OFF_B1 + col];
        float acc[4];
        #pragma unroll
        for (int q = 0; q < 4; q++) {
            const int r = 4 * h + q;
            float a = bb;
            #pragma unroll
            for (int d = 0; d < 14; d++) a = fmaf(sF[r * 16 + d], w[d], a);
            acc[q] = fmaxf(a, 0.f);
        }
        reinterpret_cast<float2*>(sA)[(2 * h) * 128 + col]     = make_float2(acc[0], acc[1]);
        reinterpret_cast<float2*>(sA)[(2 * h + 1) * 128 + col] = make_float2(acc[2], acc[3]);
    }

    // ---- W2 ready? ----
    mbar_wait(mbarB, 0);
    __syncthreads();

    // h2 = relu(h1 @ W2 + b2) : sA -> sB
    dense128p(sA, sm + OFF_W2, sm + OFF_B2, sB, col, h);

    mbar_wait(mbarC, 0);
    __syncthreads();

    // m = relu(h2 @ Wm1 + bm1) : sB -> sA
    dense128p(sB, sm + OFF_WM1, sm + OFF_BM1, sA, col, h);
    __syncthreads();

    // o = m @ Wm2 + bm2 : 256 threads = 8 rows x 4 cols x 8 k-slices
    {
        const int r = tid >> 5, c = (tid >> 3) & 3, s = tid & 7;
        const int pair = r >> 1, e = r & 1;
        float p = 0.f;
        #pragma unroll
        for (int i = 0; i < 16; i++) {
            const int k = s * 16 + i;
            p = fmaf(sA[pair * 256 + 2 * k + e], sm[OFF_WM2 + k * 4 + c], p);
        }
        sB[tid] = p;  // sB dead, reuse as scratch
    }
    __syncthreads();
    if (tid < ROWS * 4) {
        const int r = tid >> 2, c = tid & 3;
        float o = sm[OFF_BM2 + c];
        #pragma unroll
        for (int s = 0; s < 8; s++) o += sB[(r << 5) | (c << 3) | s];
        sF[r * 16 + c] = o;
    }
    __syncthreads();

    // write: mu replicated x32, std = exp(-5 + 3.5*(tanh(o)+1)) replicated x32
    #pragma unroll
    for (int i = tid; i < ROWS * 128; i += NT) {
        const int r = i >> 7, j = i & 127;
        const size_t b = (size_t)(base + r);
        if (j < 64) {
            out[b * 64 + j] = sF[r * 16 + (j & 1)];
        } else {
            const int jj = j - 64;
            const float lc = sF[r * 16 + 2 + (jj & 1)];
            const float t  = tanhf(lc);
            out[(size_t)std_off + b * 64 + jj] = __expf(-5.0f + 3.5f * (t + 1.0f));
        }
    }
}

extern "C" void kernel_launch(void* const* d_in, const int* in_sizes, int n_in,
                              void* d_out, int out_size) {
    const float* obs = (const float*)d_in[0];
    const float* W1  = (const float*)d_in[1];
    const float* b1  = (const float*)d_in[2];
    const float* W2  = (const float*)d_in[3];
    const float* b2  = (const float*)d_in[4];
    const float* Wm1 = (const float*)d_in[5];
    const float* bm1 = (const float*)d_in[6];
    const float* Wm2 = (const float*)d_in[7];
    const float* bm2 = (const float*)d_in[8];
    float* out = (float*)d_out;

    const int bs = in_sizes[0] / 512;
    const int std_off = bs * 64;
    const int grid = bs / ROWS;

    cudaFuncSetAttribute(gcnn_actor_kernel,
                         cudaFuncAttributeMaxDynamicSharedMemorySize, SMEM_BYTES);
    gcnn_actor_kernel<<<grid, NT, SMEM_BYTES>>>(obs, W1, b1, W2, b2, Wm1, bm1,
                                                Wm2, bm2, out, std_off);
}